// round 16
// baseline (speedup 1.0000x reference)
#include <cuda_runtime.h>
#include <cuda_fp16.h>
#include <stdint.h>

#define B_    512
#define T_    76
#define HIST  10
#define H_    256
#define NSTEP 64
#define MLPH  15000
#define K1    130
#define NC2H  235

__device__ __align__(16) __half g_mlph[8][NC2H * 4096];
__device__ __align__(16) __half g_W2h[(size_t)64 * NC2H * 4096];
__device__ __align__(16) __half g_hh[2][8][16][8192];
__device__ __align__(16) float g_h7row[16][32][256];
__device__ __align__(16) float g_c[8][B_][H_];
__device__ __align__(16) __half g_Wph[4194304];
__device__ __align__(16) __half g_Wih0h[16][1024];
__device__ unsigned g_prog[256];

#define U(x) __float_as_uint(x)
__device__ __forceinline__ void mma16(float c[4], uint32_t a0, uint32_t a1, uint32_t a2, uint32_t a3,
                                      uint32_t b0, uint32_t b1) {
    asm volatile("mma.sync.aligned.m16n8k16.row.col.f32.f16.f16.f32 "
                 "{%0,%1,%2,%3},{%4,%5,%6,%7},{%8,%9},{%0,%1,%2,%3};\n"
                 : "+f"(c[0]), "+f"(c[1]), "+f"(c[2]), "+f"(c[3])
                 : "r"(a0), "r"(a1), "r"(a2), "r"(a3), "r"(b0), "r"(b1));
}
__device__ __forceinline__ float sigf(float x) { return __fdividef(1.f, 1.f + __expf(-x)); }
__device__ __forceinline__ float tanhf_(float x) { return 2.f * sigf(2.f * x) - 1.f; }
__device__ __forceinline__ float tanhapx(float x) {
    float y; asm("tanh.approx.f32 %0, %1;" : "=f"(y) : "f"(x)); return y;
}
__device__ __forceinline__ void cpa16(void* s, const void* g) {
    uint32_t sa = (uint32_t)__cvta_generic_to_shared(s);
    asm volatile("cp.async.cg.shared.global [%0], [%1], 16;" :: "r"(sa), "l"(g));
}
#define CP_COMMIT() asm volatile("cp.async.commit_group;\n")
#define CP_WAIT(n)  asm volatile("cp.async.wait_group %0;\n" :: "n"(n))

__device__ __forceinline__ uint4 ldcg4(const uint4* p) {
    uint4 v;
    asm volatile("ld.global.cg.v4.u32 {%0,%1,%2,%3}, [%4];"
                 : "=r"(v.x), "=r"(v.y), "=r"(v.z), "=r"(v.w) : "l"(p));
    return v;
}

__device__ __forceinline__ int hfrag16(int r, int k) {
    const int f4 = ((k >> 4) * 2 + ((r >> 4) & 1)) * 32 + (r & 7) * 4 + ((k & 7) >> 1);
    const int sub = (((k >> 3) & 1) * 2 + ((r >> 3) & 1)) * 2 + (k & 1);
    return f4 * 8 + sub;
}
__device__ __forceinline__ int hfragA64(int r, int k) {
    const int f4 = ((k >> 4) * 4 + (r >> 4)) * 32 + (r & 7) * 4 + ((k & 7) >> 1);
    const int sub = (((k >> 3) & 1) * 2 + ((r >> 3) & 1)) * 2 + (k & 1);
    return f4 * 8 + sub;
}

__device__ __forceinline__ void mma_chunk16g(const uint4* Ac, const uint4* Bc,
                                             float (&acc)[4][4], int wm, int wn, int lane) {
#pragma unroll
    for (int ks = 0; ks < 4; ks++) {
        uint4 a = Ac[(ks * 4 + wm) * 32 + lane];
        uint4 p = Bc[((ks * 2 + wn) * 2 + 0) * 32 + lane];
        uint4 q = Bc[((ks * 2 + wn) * 2 + 1) * 32 + lane];
        mma16(acc[0], a.x, a.y, a.z, a.w, p.x, p.y);
        mma16(acc[1], a.x, a.y, a.z, a.w, p.z, p.w);
        mma16(acc[2], a.x, a.y, a.z, a.w, q.x, q.y);
        mma16(acc[3], a.x, a.y, a.z, a.w, q.z, q.w);
    }
}

// ---- prep: rollout weights -> fp16 B-fragments, gate-interleaved ----
__global__ void __launch_bounds__(256) k_prep_w(const float* __restrict__ Whh0,
                                                const float* __restrict__ Wih,
                                                const float* __restrict__ Whh) {
    const int idx = blockIdx.x * 256 + threadIdx.x;
    const int e = idx & 4095;
    const int c = (idx >> 12) & 7, bh = (idx >> 15) & 15, l = (idx >> 19) & 7;
    const int f4 = e >> 3, sub = e & 7;
    const int lane = f4 & 31, jp = (f4 >> 5) & 1, wn = (f4 >> 6) & 1, ks = (f4 >> 7) & 3;
    const int g = lane >> 2, tq = lane & 3;
    const int j = jp * 2 + (sub >> 2);
    const int kk = ((sub >> 1) & 1) * 8 + 2 * tq + (sub & 1);
    const int k = (c & 3) * 64 + ks * 16 + kk;
    const int s = c >> 2;
    const int n = j * 256 + bh * 16 + wn * 8 + g;
    float v = 0.f;
    if (l == 0) { if (s == 0) v = Whh0[n * 256 + k]; }
    else v = (s == 0) ? Whh[(size_t)(l - 1) * 262144 + n * 256 + k]
                      : Wih[(size_t)(l - 1) * 262144 + n * 256 + k];
    g_Wph[idx] = __float2half_rn(v);
}

// ---- prep: W2 -> fp16 B-fragments via coalesced smem transpose ----
__global__ void __launch_bounds__(256) k_prep_w2t(const float* __restrict__ W2) {
    const int bn = blockIdx.x / NC2H, kc = blockIdx.x - bn * NC2H;
    const int tid = threadIdx.x;
    __shared__ float s[64][65];
#pragma unroll
    for (int q = 0; q < 4; q++) {
        const int f = tid + q * 256;
        const int n = f >> 4, kq = (f & 15) << 2;
        const int gk = kc * 64 + kq;
        float4 v;
        const float* p = W2 + (size_t)(bn * 64 + n) * MLPH;
        if (gk + 3 < MLPH) v = *(const float4*)(p + gk);
        else {
            v.x = (gk + 0 < MLPH) ? p[gk + 0] : 0.f;
            v.y = (gk + 1 < MLPH) ? p[gk + 1] : 0.f;
            v.z = (gk + 2 < MLPH) ? p[gk + 2] : 0.f;
            v.w = (gk + 3 < MLPH) ? p[gk + 3] : 0.f;
        }
        s[n][kq] = v.x; s[n][kq + 1] = v.y; s[n][kq + 2] = v.z; s[n][kq + 3] = v.w;
    }
    __syncthreads();
    uint4* dst = ((uint4*)g_W2h) + (size_t)(bn * NC2H + kc) * 512;
#pragma unroll
    for (int q = 0; q < 2; q++) {
        const int f4 = tid + q * 256;
        const int lane = f4 & 31, jp = (f4 >> 5) & 1, wn = (f4 >> 6) & 1, ks = (f4 >> 7) & 3;
        const int g = lane >> 2, tq = lane & 3;
        __half h[8];
#pragma unroll
        for (int sub = 0; sub < 8; sub++) {
            const int j = jp * 2 + (sub >> 2);
            const int kk = ((sub >> 1) & 1) * 8 + 2 * tq + (sub & 1);
            const int col = j * 16 + wn * 8 + g;
            h[sub] = __float2half_rn(s[col][ks * 16 + kk]);
        }
        dst[f4] = *(const uint4*)h;
    }
}

__global__ void __launch_bounds__(256) k_prep_small(const float* __restrict__ Wih0) {
    const int i = blockIdx.x * 256 + threadIdx.x;
    if (i < 16384) {
        const int bh = i >> 10, e = i & 1023;
        const int f4 = e >> 3, sub = e & 7;
        const int lane = f4 & 31, jp = (f4 >> 5) & 1, wn = (f4 >> 6) & 1;
        const int g = lane >> 2, tq = lane & 3;
        const int j = jp * 2 + (sub >> 2);
        const int k = ((sub >> 1) & 1) * 8 + 2 * tq + (sub & 1);
        const int n = j * 256 + bh * 16 + wn * 8 + g;
        g_Wih0h[bh][e] = __float2half_rn((k < 14) ? Wih0[n * 14 + k] : 0.f);
    } else if (i < 16384 + 20480) {
        const int j = i - 16384;
        const int b = j / 40, k = MLPH + j % 40;
        g_mlph[b >> 6][(k >> 6) * 4096 + hfragA64(b & 63, k & 63)] = __float2half_rn(0.f);
    } else if (i < 16384 + 20480 + 256) {
        g_prog[i - 16384 - 20480] = 0u;
    }
}

// ---- GEMM1 ----
__global__ void __launch_bounds__(256) k_gemm1(const float* __restrict__ states,
                                               const float* __restrict__ acts,
                                               const float* __restrict__ W1,
                                               const float* __restrict__ b1) {
    const int bm = blockIdx.x & 15, bn = blockIdx.x >> 4, n0 = bn * 128;
    const int tid = threadIdx.x;
    __shared__ float enc_s[32][132];
    __shared__ float w_s[128][33];
    for (int i = tid; i < 32 * K1; i += 256) {
        const int r = i / K1, k = i % K1, b = bm * 32 + r;
        const int tt = k / 13, j = k % 13;
        enc_s[r][k] = (j < 9) ? states[(b * T_ + tt) * 12 + 3 + j]
                              : acts[(b * T_ + tt) * 4 + (j - 9)];
    }
    float acc[4][4];
#pragma unroll
    for (int a = 0; a < 4; a++)
#pragma unroll
        for (int b = 0; b < 4; b++) acc[a][b] = 0.f;
    const int tr = tid >> 5, tc = tid & 31;
    for (int k0 = 0; k0 < K1; k0 += 32) {
        const int kn = min(32, K1 - k0);
        __syncthreads();
        for (int i = tid; i < 4096; i += 256) {
            const int c = i >> 5, kk = i & 31, n = n0 + c;
            w_s[c][kk] = (kk < kn && n < MLPH) ? W1[n * K1 + k0 + kk] : 0.f;
        }
        __syncthreads();
        for (int kk = 0; kk < kn; kk++) {
            float a[4], w[4];
#pragma unroll
            for (int x = 0; x < 4; x++) a[x] = enc_s[tr + 8 * x][k0 + kk];
#pragma unroll
            for (int y = 0; y < 4; y++) w[y] = w_s[tc + 32 * y][kk];
#pragma unroll
            for (int x = 0; x < 4; x++)
#pragma unroll
                for (int y = 0; y < 4; y++) acc[x][y] += a[x] * w[y];
        }
    }
#pragma unroll
    for (int x = 0; x < 4; x++)
#pragma unroll
        for (int y = 0; y < 4; y++) {
            const int b = bm * 32 + tr + 8 * x, n = n0 + tc + 32 * y;
            if (n < MLPH)
                g_mlph[b >> 6][(n >> 6) * 4096 + hfragA64(b & 63, n & 63)] =
                    __float2half_rn(fmaxf(acc[x][y] + b1[n], 0.f));
        }
}

// ---- GEMM2: fp16, 4-buffer pipeline, 2 CTA/SM ----
__global__ void __launch_bounds__(256, 2) k_gemm2(const float* __restrict__ b2) {
    const int bm = blockIdx.x & 7, bn = blockIdx.x >> 3;
    const int tid = threadIdx.x;
    const int warp = tid >> 5, lane = tid & 31;
    const int wm = warp >> 1, wn = warp & 1;
    const int g = lane >> 2, tq = lane & 3;
    extern __shared__ __align__(16) uint4 s4[];
    uint4* A4 = s4;
    uint4* B4 = s4 + 4 * 512;
    const uint4* Asrc = (const uint4*)g_mlph[bm];
    const uint4* Bsrc = ((const uint4*)g_W2h) + (size_t)bn * (NC2H * 512);

    float acc[4][4];
#pragma unroll
    for (int j = 0; j < 4; j++)
#pragma unroll
        for (int d = 0; d < 4; d++) acc[j][d] = 0.f;

    auto stage = [&](int s, int c) {
#pragma unroll
        for (int q = 0; q < 2; q++) {
            cpa16(&A4[s * 512 + tid + q * 256], Asrc + (size_t)c * 512 + tid + q * 256);
            cpa16(&B4[s * 512 + tid + q * 256], Bsrc + (size_t)c * 512 + tid + q * 256);
        }
        CP_COMMIT();
    };
    stage(0, 0); stage(1, 1); stage(2, 2);
    for (int c = 0; c < NC2H; c++) {
        const int rem = NC2H - 1 - c;
        if (rem >= 2) CP_WAIT(2); else if (rem == 1) CP_WAIT(1); else CP_WAIT(0);
        __syncthreads();
        if (c + 3 < NC2H) stage((c + 3) & 3, c + 3);
        mma_chunk16g(A4 + (c & 3) * 512, B4 + (c & 3) * 512, acc, wm, wn, lane);
    }
#pragma unroll
    for (int j = 0; j < 4; j++)
#pragma unroll
        for (int d = 0; d < 4; d++) {
            const int r = wm * 16 + g + ((d & 2) ? 8 : 0);
            const int col = j * 16 + wn * 8 + tq * 2 + (d & 1);
            const int n = bn * 64 + col;
            const float v = acc[j][d] + b2[n];
            const int l = n >> 9, rem2 = n & 511;
            if (rem2 < H_)
                g_hh[1][l][bm * 2 + (r >> 5)][hfrag16(r & 31, rem2)] = __float2half_rn(v);
            else
                g_c[l][bm * 64 + r][rem2 - H_] = v;
        }
}

// ---- rollout: register operands, split spin, cross-layer prefetch ----
__global__ void __launch_bounds__(128, 2) k_rollout(
    const float* __restrict__ states, const float* __restrict__ acts,
    const float* __restrict__ dts,
    const float* __restrict__ bih0, const float* __restrict__ bhh0,
    const float* __restrict__ bih, const float* __restrict__ bhh,
    const float* __restrict__ Wfc, const float* __restrict__ bfc,
    float* __restrict__ out)
{
    const int rg = blockIdx.x >> 4, bh = blockIdx.x & 15;
    const int tid = threadIdx.x;
    const int warp = tid >> 5, lane = tid & 31;
    const int wm = warp >> 1, wn = warp & 1;
    const int g = lane >> 2, tq = lane & 3;
    const int row0 = rg * 32, hc0 = bh * 16;
    const int aoff = wm * 32 + lane;
    const int boff = wn * 64 + lane;

    extern __shared__ __align__(16) float sm[];
    uint4* AXh = (uint4*)sm;
    uint4* BXh = (uint4*)(sm + 256);
    float (*Gs)[68]   = (float(*)[68])(sm + 768);
    float (*xs)[16]   = (float(*)[16])(sm + 2944);
    float (*bias)[64] = (float(*)[64])(sm + 3456);
    float* Wfcs       = sm + 3968;

    cpa16(&BXh[tid], ((const uint4*)g_Wih0h[bh]) + tid);
    CP_COMMIT();

    for (int i = tid; i < 512; i += 128) {
        const int l = i >> 6, gc = i & 63;
        const int n = (gc >> 4) * 256 + hc0 + (gc & 15);
        bias[l][gc] = (l == 0) ? __ldg(&bih0[n]) + __ldg(&bhh0[n])
                               : __ldg(&bih[(l - 1) * 1024 + n]) + __ldg(&bhh[(l - 1) * 1024 + n]);
    }
    for (int i = tid; i < 2304; i += 128) Wfcs[i] = __ldg(&Wfc[i]);

    float c_reg[8][4];
#pragma unroll
    for (int l = 0; l < 8; l++)
#pragma unroll
        for (int d = 0; d < 4; d++) {
            const int r = wm * 16 + g + ((d & 2) ? 8 : 0);
            const int hc = wn * 8 + tq * 2 + (d & 1);
            c_reg[l][d] = __ldcg(&g_c[l][row0 + r][hc0 + hc]);
        }
    for (int i = tid; i < 288; i += 128) {
        const int r = i / 9, j = i % 9;
        xs[r][1 + j] = states[((row0 + r) * T_ + HIST) * 12 + 3 + j];
    }
    if (tid < 64) xs[tid >> 1][14 + (tid & 1)] = 0.f;
    CP_WAIT(0);
    __syncthreads();

    for (int t = 0; t < NSTEP; t++) {
        const int cur = t & 1, old = cur ^ 1;
        if (tid < 32) xs[tid][0] = dts[(row0 + tid) * T_ + HIST + 1 + t];
        {
            const int r = tid >> 2, j = tid & 3;
            xs[r][10 + j] = acts[((row0 + r) * T_ + HIST + t) * 4 + j];
        }
        __syncthreads();

        uint4 ar[2][4], br[2][8];

        for (int l = 0; l < 8; l++) {
            float acc[4][4];
#pragma unroll
            for (int j = 0; j < 4; j++)
#pragma unroll
                for (int d = 0; d < 4; d++) acc[j][d] = 0.f;

            const uint4* Bb = ((const uint4*)g_Wph) + (size_t)(l * 16 + bh) * 4096;
            const uint4* Ah0 = (const uint4*)&g_hh[old][l][rg][0];
            const uint4* Ah1 = (l > 0) ? (const uint4*)&g_hh[cur][l - 1][rg][0] : Ah0;

            if (l == 0) {
                // load chunk 0 (no preload across step boundary)
#pragma unroll
                for (int ks = 0; ks < 4; ks++) {
                    ar[0][ks] = ldcg4(Ah0 + ks * 64 + aoff);
                    br[0][ks * 2]     = __ldg(Bb + ks * 128 + boff);
                    br[0][ks * 2 + 1] = __ldg(Bb + ks * 128 + 32 + boff);
                }
                if (tid < 64) {
                    const int mt = tid >> 5, ln = tid & 31;
                    const int gg = ln >> 2, tt = ln & 3;
                    uint4 v;
                    __half2 h0 = __floats2half2_rn(xs[mt * 16 + gg][2 * tt], xs[mt * 16 + gg][2 * tt + 1]);
                    __half2 h1 = __floats2half2_rn(xs[mt * 16 + gg + 8][2 * tt], xs[mt * 16 + gg + 8][2 * tt + 1]);
                    __half2 h2 = __floats2half2_rn(xs[mt * 16 + gg][8 + 2 * tt], xs[mt * 16 + gg][8 + 2 * tt + 1]);
                    __half2 h3 = __floats2half2_rn(xs[mt * 16 + gg + 8][8 + 2 * tt], xs[mt * 16 + gg + 8][8 + 2 * tt + 1]);
                    v.x = *(uint32_t*)&h0; v.y = *(uint32_t*)&h1;
                    v.z = *(uint32_t*)&h2; v.w = *(uint32_t*)&h3;
                    AXh[mt * 32 + ln] = v;
                }
                __syncthreads();
                {
                    uint4 a = AXh[wm * 32 + lane];
                    uint4 p = BXh[(wn * 2 + 0) * 32 + lane];
                    uint4 q = BXh[(wn * 2 + 1) * 32 + lane];
                    mma16(acc[0], a.x, a.y, a.z, a.w, p.x, p.y);
                    mma16(acc[1], a.x, a.y, a.z, a.w, p.z, p.w);
                    mma16(acc[2], a.x, a.y, a.z, a.w, q.x, q.y);
                    mma16(acc[3], a.x, a.y, a.z, a.w, q.z, q.w);
                }
#pragma unroll
                for (int c = 0; c < 4; c++) {
                    const int nb = (c + 1) & 1, cb = c & 1;
                    if (c + 1 < 4) {
                        const uint4* An = Ah0 + (c + 1) * 256;
                        const uint4* Bn = Bb + (c + 1) * 512;
#pragma unroll
                        for (int ks = 0; ks < 4; ks++) {
                            ar[nb][ks] = ldcg4(An + ks * 64 + aoff);
                            br[nb][ks * 2]     = __ldg(Bn + ks * 128 + boff);
                            br[nb][ks * 2 + 1] = __ldg(Bn + ks * 128 + 32 + boff);
                        }
                    }
#pragma unroll
                    for (int ks = 0; ks < 4; ks++) {
                        uint4 a = ar[cb][ks], p = br[cb][ks * 2], q = br[cb][ks * 2 + 1];
                        mma16(acc[0], a.x, a.y, a.z, a.w, p.x, p.y);
                        mma16(acc[1], a.x, a.y, a.z, a.w, p.z, p.w);
                        mma16(acc[2], a.x, a.y, a.z, a.w, q.x, q.y);
                        mma16(acc[3], a.x, a.y, a.z, a.w, q.z, q.w);
                    }
                }
            } else {
                // chunk 0 is already preloaded in ar[0]/br[0]
#pragma unroll
                for (int c = 0; c < 8; c++) {
                    const int nb = (c + 1) & 1, cb = c & 1;
                    if (c == 3) {   // chunks 4,5 need h-cols from bh 0-7
                        const unsigned tgt = (unsigned)(t * 8 + l);
                        if (tid < 8) {
                            unsigned v;
                            const unsigned* fp = &g_prog[rg * 16 + tid];
                            do {
                                asm volatile("ld.acquire.gpu.global.u32 %0, [%1];" : "=r"(v) : "l"(fp));
                                if (v >= tgt) break;
                                __nanosleep(32);
                            } while (1);
                        }
                        __syncthreads();
                    } else if (c == 5) {   // chunks 6,7 need bh 8-15
                        const unsigned tgt = (unsigned)(t * 8 + l);
                        if (tid < 8) {
                            unsigned v;
                            const unsigned* fp = &g_prog[rg * 16 + 8 + tid];
                            do {
                                asm volatile("ld.acquire.gpu.global.u32 %0, [%1];" : "=r"(v) : "l"(fp));
                                if (v >= tgt) break;
                                __nanosleep(32);
                            } while (1);
                        }
                        __syncthreads();
                    }
                    if (c + 1 < 8) {
                        const uint4* An = (c + 1 < 4) ? Ah0 + (c + 1) * 256 : Ah1 + (c - 3) * 256;
                        const uint4* Bn = Bb + (c + 1) * 512;
#pragma unroll
                        for (int ks = 0; ks < 4; ks++) {
                            ar[nb][ks] = ldcg4(An + ks * 64 + aoff);
                            br[nb][ks * 2]     = __ldg(Bn + ks * 128 + boff);
                            br[nb][ks * 2 + 1] = __ldg(Bn + ks * 128 + 32 + boff);
                        }
                    }
#pragma unroll
                    for (int ks = 0; ks < 4; ks++) {
                        uint4 a = ar[cb][ks], p = br[cb][ks * 2], q = br[cb][ks * 2 + 1];
                        mma16(acc[0], a.x, a.y, a.z, a.w, p.x, p.y);
                        mma16(acc[1], a.x, a.y, a.z, a.w, p.z, p.w);
                        mma16(acc[2], a.x, a.y, a.z, a.w, q.x, q.y);
                        mma16(acc[3], a.x, a.y, a.z, a.w, q.z, q.w);
                    }
                }
            }

            // preload next layer's chunk 0 (dependency-free) before epilogue
            if (l < 7) {
                const uint4* An = (const uint4*)&g_hh[old][l + 1][rg][0];
                const uint4* Bn = ((const uint4*)g_Wph) + (size_t)((l + 1) * 16 + bh) * 4096;
#pragma unroll
                for (int ks = 0; ks < 4; ks++) {
                    ar[0][ks] = ldcg4(An + ks * 64 + aoff);
                    br[0][ks * 2]     = __ldg(Bn + ks * 128 + boff);
                    br[0][ks * 2 + 1] = __ldg(Bn + ks * 128 + 32 + boff);
                }
            }

            // register LSTM epilogue (tanh.approx), packed half2 h-stores
            __half* hdst = &g_hh[cur][l][rg][0];
#pragma unroll
            for (int dp = 0; dp < 2; dp++) {
                const int r = wm * 16 + g + (dp ? 8 : 0);
                const int hcb = wn * 8 + tq * 2;
                __half hv2[2];
#pragma unroll
                for (int e = 0; e < 2; e++) {
                    const int d = dp * 2 + e;
                    const float iG = acc[0][d] + bias[l][hcb + e];
                    const float fG = acc[1][d] + bias[l][16 + hcb + e];
                    const float gG = acc[2][d] + bias[l][32 + hcb + e];
                    const float oG = acc[3][d] + bias[l][48 + hcb + e];
                    const float iS = 0.5f + 0.5f * tanhapx(0.5f * iG);
                    const float fS = 0.5f + 0.5f * tanhapx(0.5f * fG);
                    const float oS = 0.5f + 0.5f * tanhapx(0.5f * oG);
                    const float cn = fS * c_reg[l][d] + iS * tanhapx(gG);
                    c_reg[l][d] = cn;
                    const float hv = oS * tanhapx(cn);
                    hv2[e] = __float2half_rn(hv);
                    if (l == 7) g_h7row[rg][r][hc0 + hcb + e] = hv;
                }
                *(__half2*)(hdst + hfrag16(r, hc0 + hcb)) = *(__half2*)hv2;
            }
            __syncthreads();
            if (tid == 0)
                asm volatile("st.release.gpu.global.u32 [%0], %1;"
                             :: "l"(&g_prog[rg * 16 + bh]),
                                "r"((unsigned)(t * 8 + l + 1)) : "memory");
        }

        if (tid < 16) {
            const unsigned tgt = (unsigned)(t * 8 + 8);
            unsigned v;
            const unsigned* fp = &g_prog[rg * 16 + tid];
            do {
                asm volatile("ld.acquire.gpu.global.u32 %0, [%1];" : "=r"(v) : "l"(fp));
                if (v >= tgt) break;
                __nanosleep(32);
            } while (1);
        }
        __syncthreads();

        // fc: 32 rows x 9 outs
        const int r2 = tid >> 2, og = tid & 3;
        float p0 = __ldg(&bfc[og]), p1 = __ldg(&bfc[og + 4]);
        float p2 = (og == 0) ? __ldg(&bfc[8]) : 0.f;
        for (int qq = 0; qq < 4; qq++) {
            __syncthreads();
#pragma unroll
            for (int q = 0; q < 4; q++) {
                const int i = tid + 128 * q;
                const int r = i >> 4, kq = (i & 15) << 2;
                float4 v = __ldcg((const float4*)&g_h7row[rg][r][qq * 64 + kq]);
                Gs[r][kq] = v.x; Gs[r][kq + 1] = v.y; Gs[r][kq + 2] = v.z; Gs[r][kq + 3] = v.w;
            }
            __syncthreads();
#pragma unroll 4
            for (int k = 0; k < 64; k++) {
                const float gv = Gs[r2][k];
                p0 += gv * Wfcs[og * 256 + qq * 64 + k];
                p1 += gv * Wfcs[(og + 4) * 256 + qq * 64 + k];
                if (og == 0) p2 += gv * Wfcs[8 * 256 + qq * 64 + k];
            }
        }
        __syncthreads();
        xs[r2][1 + og] = p0;
        xs[r2][1 + og + 4] = p1;
        if (og == 0) xs[r2][9] = p2;
        if (bh == 0) {
            out[(size_t)(row0 + r2) * (NSTEP * 9) + t * 9 + og] = p0;
            out[(size_t)(row0 + r2) * (NSTEP * 9) + t * 9 + og + 4] = p1;
            if (og == 0) out[(size_t)(row0 + r2) * (NSTEP * 9) + t * 9 + 8] = p2;
        }
        __syncthreads();
    }
}

extern "C" void kernel_launch(void* const* d_in, const int* in_sizes, int n_in,
                              void* d_out, int out_size) {
    const float* states = (const float*)d_in[0];
    const float* acts   = (const float*)d_in[1];
    const float* dts    = (const float*)d_in[2];
    const float* W1     = (const float*)d_in[3];
    const float* b1     = (const float*)d_in[4];
    const float* W2     = (const float*)d_in[5];
    const float* b2     = (const float*)d_in[6];
    const float* Wih0   = (const float*)d_in[7];
    const float* Whh0   = (const float*)d_in[8];
    const float* bih0   = (const float*)d_in[9];
    const float* bhh0   = (const float*)d_in[10];
    const float* Wih    = (const float*)d_in[11];
    const float* Whh    = (const float*)d_in[12];
    const float* bih    = (const float*)d_in[13];
    const float* bhh    = (const float*)d_in[14];
    const float* Wfc    = (const float*)d_in[15];
    const float* bfc    = (const float*)d_in[16];
    float* out = (float*)d_out;

    const int sm2 = 8 * 512 * 16;
    const int smr = 6272 * 4;
    cudaFuncSetAttribute(k_gemm2, cudaFuncAttributeMaxDynamicSharedMemorySize, sm2);
    cudaFuncSetAttribute(k_rollout, cudaFuncAttributeMaxDynamicSharedMemorySize, smr);

    k_prep_w<<<16384, 256>>>(Whh0, Wih, Whh);
    k_prep_w2t<<<64 * NC2H, 256>>>(W2);
    k_prep_small<<<146, 256>>>(Wih0);
    k_gemm1<<<16 * 118, 256>>>(states, acts, W1, b1);
    k_gemm2<<<512, 256, sm2>>>(b2);
    k_rollout<<<256, 128, smr>>>(states, acts, dts, bih0, bhh0,
                                 bih, bhh, Wfc, bfc, out);
}

// round 17
// speedup vs baseline: 1.0969x; 1.0969x over previous
#include <cuda_runtime.h>
#include <cuda_fp16.h>
#include <stdint.h>

#define B_    512
#define T_    76
#define HIST  10
#define H_    256
#define NSTEP 64
#define MLPH  15000
#define K1    130
#define NC2H  235

__device__ __align__(16) __half g_mlph[8][NC2H * 4096];
__device__ __align__(16) __half g_W2h[(size_t)64 * NC2H * 4096];
__device__ __align__(16) __half g_hh[2][8][16][8192];
__device__ __align__(16) float g_h7row[16][32][256];
__device__ __align__(16) float g_c[8][B_][H_];
__device__ __align__(16) __half g_Wph[4194304];
__device__ __align__(16) __half g_Wih0h[16][1024];
__device__ unsigned g_prog[256];

#define U(x) __float_as_uint(x)
__device__ __forceinline__ void mma16(float c[4], uint32_t a0, uint32_t a1, uint32_t a2, uint32_t a3,
                                      uint32_t b0, uint32_t b1) {
    asm volatile("mma.sync.aligned.m16n8k16.row.col.f32.f16.f16.f32 "
                 "{%0,%1,%2,%3},{%4,%5,%6,%7},{%8,%9},{%0,%1,%2,%3};\n"
                 : "+f"(c[0]), "+f"(c[1]), "+f"(c[2]), "+f"(c[3])
                 : "r"(a0), "r"(a1), "r"(a2), "r"(a3), "r"(b0), "r"(b1));
}
__device__ __forceinline__ float tanhapx(float x) {
    float y; asm("tanh.approx.f32 %0, %1;" : "=f"(y) : "f"(x)); return y;
}
__device__ __forceinline__ void cpa16(void* s, const void* g) {
    uint32_t sa = (uint32_t)__cvta_generic_to_shared(s);
    asm volatile("cp.async.cg.shared.global [%0], [%1], 16;" :: "r"(sa), "l"(g));
}
#define CP_COMMIT() asm volatile("cp.async.commit_group;\n")
#define CP_WAIT(n)  asm volatile("cp.async.wait_group %0;\n" :: "n"(n))

__device__ __forceinline__ uint4 ldcg4(const uint4* p) {
    uint4 v;
    asm volatile("ld.global.cg.v4.u32 {%0,%1,%2,%3}, [%4];"
                 : "=r"(v.x), "=r"(v.y), "=r"(v.z), "=r"(v.w) : "l"(p));
    return v;
}

__device__ __forceinline__ int hfrag16(int r, int k) {
    const int f4 = ((k >> 4) * 2 + ((r >> 4) & 1)) * 32 + (r & 7) * 4 + ((k & 7) >> 1);
    const int sub = (((k >> 3) & 1) * 2 + ((r >> 3) & 1)) * 2 + (k & 1);
    return f4 * 8 + sub;
}
__device__ __forceinline__ int hfragA64(int r, int k) {
    const int f4 = ((k >> 4) * 4 + (r >> 4)) * 32 + (r & 7) * 4 + ((k & 7) >> 1);
    const int sub = (((k >> 3) & 1) * 2 + ((r >> 3) & 1)) * 2 + (k & 1);
    return f4 * 8 + sub;
}

__device__ __forceinline__ void mma_chunk16g(const uint4* Ac, const uint4* Bc,
                                             float (&acc)[4][4], int wm, int wn, int lane) {
#pragma unroll
    for (int ks = 0; ks < 4; ks++) {
        uint4 a = Ac[(ks * 4 + wm) * 32 + lane];
        uint4 p = Bc[((ks * 2 + wn) * 2 + 0) * 32 + lane];
        uint4 q = Bc[((ks * 2 + wn) * 2 + 1) * 32 + lane];
        mma16(acc[0], a.x, a.y, a.z, a.w, p.x, p.y);
        mma16(acc[1], a.x, a.y, a.z, a.w, p.z, p.w);
        mma16(acc[2], a.x, a.y, a.z, a.w, q.x, q.y);
        mma16(acc[3], a.x, a.y, a.z, a.w, q.z, q.w);
    }
}

// ---- prep: rollout weights -> fp16 B-fragments, gate-interleaved ----
__global__ void __launch_bounds__(256) k_prep_w(const float* __restrict__ Whh0,
                                                const float* __restrict__ Wih,
                                                const float* __restrict__ Whh) {
    const int idx = blockIdx.x * 256 + threadIdx.x;
    const int e = idx & 4095;
    const int c = (idx >> 12) & 7, bh = (idx >> 15) & 15, l = (idx >> 19) & 7;
    const int f4 = e >> 3, sub = e & 7;
    const int lane = f4 & 31, jp = (f4 >> 5) & 1, wn = (f4 >> 6) & 1, ks = (f4 >> 7) & 3;
    const int g = lane >> 2, tq = lane & 3;
    const int j = jp * 2 + (sub >> 2);
    const int kk = ((sub >> 1) & 1) * 8 + 2 * tq + (sub & 1);
    const int k = (c & 3) * 64 + ks * 16 + kk;
    const int s = c >> 2;
    const int n = j * 256 + bh * 16 + wn * 8 + g;
    float v = 0.f;
    if (l == 0) { if (s == 0) v = Whh0[n * 256 + k]; }
    else v = (s == 0) ? Whh[(size_t)(l - 1) * 262144 + n * 256 + k]
                      : Wih[(size_t)(l - 1) * 262144 + n * 256 + k];
    g_Wph[idx] = __float2half_rn(v);
}

// ---- prep: W2 -> fp16 B-fragments via coalesced smem transpose ----
__global__ void __launch_bounds__(256) k_prep_w2t(const float* __restrict__ W2) {
    const int bn = blockIdx.x / NC2H, kc = blockIdx.x - bn * NC2H;
    const int tid = threadIdx.x;
    __shared__ float s[64][65];
#pragma unroll
    for (int q = 0; q < 4; q++) {
        const int f = tid + q * 256;
        const int n = f >> 4, kq = (f & 15) << 2;
        const int gk = kc * 64 + kq;
        float4 v;
        const float* p = W2 + (size_t)(bn * 64 + n) * MLPH;
        if (gk + 3 < MLPH) v = *(const float4*)(p + gk);
        else {
            v.x = (gk + 0 < MLPH) ? p[gk + 0] : 0.f;
            v.y = (gk + 1 < MLPH) ? p[gk + 1] : 0.f;
            v.z = (gk + 2 < MLPH) ? p[gk + 2] : 0.f;
            v.w = (gk + 3 < MLPH) ? p[gk + 3] : 0.f;
        }
        s[n][kq] = v.x; s[n][kq + 1] = v.y; s[n][kq + 2] = v.z; s[n][kq + 3] = v.w;
    }
    __syncthreads();
    uint4* dst = ((uint4*)g_W2h) + (size_t)(bn * NC2H + kc) * 512;
#pragma unroll
    for (int q = 0; q < 2; q++) {
        const int f4 = tid + q * 256;
        const int lane = f4 & 31, jp = (f4 >> 5) & 1, wn = (f4 >> 6) & 1, ks = (f4 >> 7) & 3;
        const int g = lane >> 2, tq = lane & 3;
        __half h[8];
#pragma unroll
        for (int sub = 0; sub < 8; sub++) {
            const int j = jp * 2 + (sub >> 2);
            const int kk = ((sub >> 1) & 1) * 8 + 2 * tq + (sub & 1);
            const int col = j * 16 + wn * 8 + g;
            h[sub] = __float2half_rn(s[col][ks * 16 + kk]);
        }
        dst[f4] = *(const uint4*)h;
    }
}

__global__ void __launch_bounds__(256) k_prep_small(const float* __restrict__ Wih0) {
    const int i = blockIdx.x * 256 + threadIdx.x;
    if (i < 16384) {
        const int bh = i >> 10, e = i & 1023;
        const int f4 = e >> 3, sub = e & 7;
        const int lane = f4 & 31, jp = (f4 >> 5) & 1, wn = (f4 >> 6) & 1;
        const int g = lane >> 2, tq = lane & 3;
        const int j = jp * 2 + (sub >> 2);
        const int k = ((sub >> 1) & 1) * 8 + 2 * tq + (sub & 1);
        const int n = j * 256 + bh * 16 + wn * 8 + g;
        g_Wih0h[bh][e] = __float2half_rn((k < 14) ? Wih0[n * 14 + k] : 0.f);
    } else if (i < 16384 + 20480) {
        const int j = i - 16384;
        const int b = j / 40, k = MLPH + j % 40;
        g_mlph[b >> 6][(k >> 6) * 4096 + hfragA64(b & 63, k & 63)] = __float2half_rn(0.f);
    } else if (i < 16384 + 20480 + 256) {
        g_prog[i - 16384 - 20480] = 0u;
    }
}

// ---- GEMM1 ----
__global__ void __launch_bounds__(256) k_gemm1(const float* __restrict__ states,
                                               const float* __restrict__ acts,
                                               const float* __restrict__ W1,
                                               const float* __restrict__ b1) {
    const int bm = blockIdx.x & 15, bn = blockIdx.x >> 4, n0 = bn * 128;
    const int tid = threadIdx.x;
    __shared__ float enc_s[32][132];
    __shared__ float w_s[128][33];
    for (int i = tid; i < 32 * K1; i += 256) {
        const int r = i / K1, k = i % K1, b = bm * 32 + r;
        const int tt = k / 13, j = k % 13;
        enc_s[r][k] = (j < 9) ? states[(b * T_ + tt) * 12 + 3 + j]
                              : acts[(b * T_ + tt) * 4 + (j - 9)];
    }
    float acc[4][4];
#pragma unroll
    for (int a = 0; a < 4; a++)
#pragma unroll
        for (int b = 0; b < 4; b++) acc[a][b] = 0.f;
    const int tr = tid >> 5, tc = tid & 31;
    for (int k0 = 0; k0 < K1; k0 += 32) {
        const int kn = min(32, K1 - k0);
        __syncthreads();
        for (int i = tid; i < 4096; i += 256) {
            const int c = i >> 5, kk = i & 31, n = n0 + c;
            w_s[c][kk] = (kk < kn && n < MLPH) ? W1[n * K1 + k0 + kk] : 0.f;
        }
        __syncthreads();
        for (int kk = 0; kk < kn; kk++) {
            float a[4], w[4];
#pragma unroll
            for (int x = 0; x < 4; x++) a[x] = enc_s[tr + 8 * x][k0 + kk];
#pragma unroll
            for (int y = 0; y < 4; y++) w[y] = w_s[tc + 32 * y][kk];
#pragma unroll
            for (int x = 0; x < 4; x++)
#pragma unroll
                for (int y = 0; y < 4; y++) acc[x][y] += a[x] * w[y];
        }
    }
#pragma unroll
    for (int x = 0; x < 4; x++)
#pragma unroll
        for (int y = 0; y < 4; y++) {
            const int b = bm * 32 + tr + 8 * x, n = n0 + tc + 32 * y;
            if (n < MLPH)
                g_mlph[b >> 6][(n >> 6) * 4096 + hfragA64(b & 63, n & 63)] =
                    __float2half_rn(fmaxf(acc[x][y] + b1[n], 0.f));
        }
}

// ---- GEMM2: fp16, 4-buffer pipeline, 2 CTA/SM ----
__global__ void __launch_bounds__(256, 2) k_gemm2(const float* __restrict__ b2) {
    const int bm = blockIdx.x & 7, bn = blockIdx.x >> 3;
    const int tid = threadIdx.x;
    const int warp = tid >> 5, lane = tid & 31;
    const int wm = warp >> 1, wn = warp & 1;
    const int g = lane >> 2, tq = lane & 3;
    extern __shared__ __align__(16) uint4 s4[];
    uint4* A4 = s4;
    uint4* B4 = s4 + 4 * 512;
    const uint4* Asrc = (const uint4*)g_mlph[bm];
    const uint4* Bsrc = ((const uint4*)g_W2h) + (size_t)bn * (NC2H * 512);

    float acc[4][4];
#pragma unroll
    for (int j = 0; j < 4; j++)
#pragma unroll
        for (int d = 0; d < 4; d++) acc[j][d] = 0.f;

    auto stage = [&](int s, int c) {
#pragma unroll
        for (int q = 0; q < 2; q++) {
            cpa16(&A4[s * 512 + tid + q * 256], Asrc + (size_t)c * 512 + tid + q * 256);
            cpa16(&B4[s * 512 + tid + q * 256], Bsrc + (size_t)c * 512 + tid + q * 256);
        }
        CP_COMMIT();
    };
    stage(0, 0); stage(1, 1); stage(2, 2);
    for (int c = 0; c < NC2H; c++) {
        const int rem = NC2H - 1 - c;
        if (rem >= 2) CP_WAIT(2); else if (rem == 1) CP_WAIT(1); else CP_WAIT(0);
        __syncthreads();
        if (c + 3 < NC2H) stage((c + 3) & 3, c + 3);
        mma_chunk16g(A4 + (c & 3) * 512, B4 + (c & 3) * 512, acc, wm, wn, lane);
    }
#pragma unroll
    for (int j = 0; j < 4; j++)
#pragma unroll
        for (int d = 0; d < 4; d++) {
            const int r = wm * 16 + g + ((d & 2) ? 8 : 0);
            const int col = j * 16 + wn * 8 + tq * 2 + (d & 1);
            const int n = bn * 64 + col;
            const float v = acc[j][d] + b2[n];
            const int l = n >> 9, rem2 = n & 511;
            if (rem2 < H_)
                g_hh[1][l][bm * 2 + (r >> 5)][hfrag16(r & 31, rem2)] = __float2half_rn(v);
            else
                g_c[l][bm * 64 + r][rem2 - H_] = v;
        }
}

// ---- rollout: register operands (r15 structure), tanh.approx epilogue ----
__global__ void __launch_bounds__(128, 2) k_rollout(
    const float* __restrict__ states, const float* __restrict__ acts,
    const float* __restrict__ dts,
    const float* __restrict__ bih0, const float* __restrict__ bhh0,
    const float* __restrict__ bih, const float* __restrict__ bhh,
    const float* __restrict__ Wfc, const float* __restrict__ bfc,
    float* __restrict__ out)
{
    const int rg = blockIdx.x >> 4, bh = blockIdx.x & 15;
    const int tid = threadIdx.x;
    const int warp = tid >> 5, lane = tid & 31;
    const int wm = warp >> 1, wn = warp & 1;
    const int g = lane >> 2, tq = lane & 3;
    const int row0 = rg * 32, hc0 = bh * 16;
    const int aoff = wm * 32 + lane;
    const int boff = wn * 64 + lane;

    extern __shared__ __align__(16) float sm[];
    uint4* AXh = (uint4*)sm;
    uint4* BXh = (uint4*)(sm + 256);
    float (*Gs)[68]   = (float(*)[68])(sm + 768);
    float (*xs)[16]   = (float(*)[16])(sm + 2944);
    float (*bias)[64] = (float(*)[64])(sm + 3456);
    float* Wfcs       = sm + 3968;

    cpa16(&BXh[tid], ((const uint4*)g_Wih0h[bh]) + tid);
    CP_COMMIT();

    for (int i = tid; i < 512; i += 128) {
        const int l = i >> 6, gc = i & 63;
        const int n = (gc >> 4) * 256 + hc0 + (gc & 15);
        bias[l][gc] = (l == 0) ? __ldg(&bih0[n]) + __ldg(&bhh0[n])
                               : __ldg(&bih[(l - 1) * 1024 + n]) + __ldg(&bhh[(l - 1) * 1024 + n]);
    }
    for (int i = tid; i < 2304; i += 128) Wfcs[i] = __ldg(&Wfc[i]);

    float c_reg[8][4];
#pragma unroll
    for (int l = 0; l < 8; l++)
#pragma unroll
        for (int d = 0; d < 4; d++) {
            const int r = wm * 16 + g + ((d & 2) ? 8 : 0);
            const int hc = wn * 8 + tq * 2 + (d & 1);
            c_reg[l][d] = __ldcg(&g_c[l][row0 + r][hc0 + hc]);
        }
    for (int i = tid; i < 288; i += 128) {
        const int r = i / 9, j = i % 9;
        xs[r][1 + j] = states[((row0 + r) * T_ + HIST) * 12 + 3 + j];
    }
    if (tid < 64) xs[tid >> 1][14 + (tid & 1)] = 0.f;
    CP_WAIT(0);
    __syncthreads();

    for (int t = 0; t < NSTEP; t++) {
        const int cur = t & 1, old = cur ^ 1;
        if (tid < 32) xs[tid][0] = dts[(row0 + tid) * T_ + HIST + 1 + t];
        {
            const int r = tid >> 2, j = tid & 3;
            xs[r][10 + j] = acts[((row0 + r) * T_ + HIST + t) * 4 + j];
        }
        __syncthreads();

        for (int l = 0; l < 8; l++) {
            float acc[4][4];
#pragma unroll
            for (int j = 0; j < 4; j++)
#pragma unroll
                for (int d = 0; d < 4; d++) acc[j][d] = 0.f;

            const uint4* Bb = ((const uint4*)g_Wph) + (size_t)(l * 16 + bh) * 4096;
            const uint4* Ah0 = (const uint4*)&g_hh[old][l][rg][0];
            const uint4* Ah1 = (l > 0) ? (const uint4*)&g_hh[cur][l - 1][rg][0] : Ah0;

            uint4 ar[2][4], br[2][8];
            // load chunk 0 (Whh on h_old — dependency-free)
#pragma unroll
            for (int ks = 0; ks < 4; ks++) {
                ar[0][ks] = ldcg4(Ah0 + ks * 64 + aoff);
                br[0][ks * 2]     = __ldg(Bb + ks * 128 + boff);
                br[0][ks * 2 + 1] = __ldg(Bb + ks * 128 + 32 + boff);
            }

            if (l == 0) {   // x-tile mma via smem
                if (tid < 64) {
                    const int mt = tid >> 5, ln = tid & 31;
                    const int gg = ln >> 2, tt = ln & 3;
                    uint4 v;
                    __half2 h0 = __floats2half2_rn(xs[mt * 16 + gg][2 * tt], xs[mt * 16 + gg][2 * tt + 1]);
                    __half2 h1 = __floats2half2_rn(xs[mt * 16 + gg + 8][2 * tt], xs[mt * 16 + gg + 8][2 * tt + 1]);
                    __half2 h2 = __floats2half2_rn(xs[mt * 16 + gg][8 + 2 * tt], xs[mt * 16 + gg][8 + 2 * tt + 1]);
                    __half2 h3 = __floats2half2_rn(xs[mt * 16 + gg + 8][8 + 2 * tt], xs[mt * 16 + gg + 8][8 + 2 * tt + 1]);
                    v.x = *(uint32_t*)&h0; v.y = *(uint32_t*)&h1;
                    v.z = *(uint32_t*)&h2; v.w = *(uint32_t*)&h3;
                    AXh[mt * 32 + ln] = v;
                }
                __syncthreads();
                {
                    uint4 a = AXh[wm * 32 + lane];
                    uint4 p = BXh[(wn * 2 + 0) * 32 + lane];
                    uint4 q = BXh[(wn * 2 + 1) * 32 + lane];
                    mma16(acc[0], a.x, a.y, a.z, a.w, p.x, p.y);
                    mma16(acc[1], a.x, a.y, a.z, a.w, p.z, p.w);
                    mma16(acc[2], a.x, a.y, a.z, a.w, q.x, q.y);
                    mma16(acc[3], a.x, a.y, a.z, a.w, q.z, q.w);
                }
#pragma unroll
                for (int c = 0; c < 4; c++) {
                    const int nb = (c + 1) & 1, cb = c & 1;
                    if (c + 1 < 4) {
                        const uint4* An = Ah0 + (c + 1) * 256;
                        const uint4* Bn = Bb + (c + 1) * 512;
#pragma unroll
                        for (int ks = 0; ks < 4; ks++) {
                            ar[nb][ks] = ldcg4(An + ks * 64 + aoff);
                            br[nb][ks * 2]     = __ldg(Bn + ks * 128 + boff);
                            br[nb][ks * 2 + 1] = __ldg(Bn + ks * 128 + 32 + boff);
                        }
                    }
#pragma unroll
                    for (int ks = 0; ks < 4; ks++) {
                        uint4 a = ar[cb][ks], p = br[cb][ks * 2], q = br[cb][ks * 2 + 1];
                        mma16(acc[0], a.x, a.y, a.z, a.w, p.x, p.y);
                        mma16(acc[1], a.x, a.y, a.z, a.w, p.z, p.w);
                        mma16(acc[2], a.x, a.y, a.z, a.w, q.x, q.y);
                        mma16(acc[3], a.x, a.y, a.z, a.w, q.z, q.w);
                    }
                }
            } else {
#pragma unroll
                for (int c = 0; c < 8; c++) {
                    const int nb = (c + 1) & 1, cb = c & 1;
                    if (c == 3) {   // spin before first h_cur[l-1] load issues
                        const unsigned tgt = (unsigned)(t * 8 + l);
                        if (tid < 16) {
                            unsigned v;
                            const unsigned* fp = &g_prog[rg * 16 + tid];
                            do {
                                asm volatile("ld.acquire.gpu.global.u32 %0, [%1];" : "=r"(v) : "l"(fp));
                                if (v >= tgt) break;
                                __nanosleep(32);
                            } while (1);
                        }
                        __syncthreads();
                    }
                    if (c + 1 < 8) {
                        const uint4* An = (c + 1 < 4) ? Ah0 + (c + 1) * 256 : Ah1 + (c - 3) * 256;
                        const uint4* Bn = Bb + (c + 1) * 512;
#pragma unroll
                        for (int ks = 0; ks < 4; ks++) {
                            ar[nb][ks] = ldcg4(An + ks * 64 + aoff);
                            br[nb][ks * 2]     = __ldg(Bn + ks * 128 + boff);
                            br[nb][ks * 2 + 1] = __ldg(Bn + ks * 128 + 32 + boff);
                        }
                    }
#pragma unroll
                    for (int ks = 0; ks < 4; ks++) {
                        uint4 a = ar[cb][ks], p = br[cb][ks * 2], q = br[cb][ks * 2 + 1];
                        mma16(acc[0], a.x, a.y, a.z, a.w, p.x, p.y);
                        mma16(acc[1], a.x, a.y, a.z, a.w, p.z, p.w);
                        mma16(acc[2], a.x, a.y, a.z, a.w, q.x, q.y);
                        mma16(acc[3], a.x, a.y, a.z, a.w, q.z, q.w);
                    }
                }
            }

            // register LSTM epilogue (tanh.approx), packed half2 h-stores
            __half* hdst = &g_hh[cur][l][rg][0];
#pragma unroll
            for (int dp = 0; dp < 2; dp++) {
                const int r = wm * 16 + g + (dp ? 8 : 0);
                const int hcb = wn * 8 + tq * 2;
                __half hv2[2];
#pragma unroll
                for (int e = 0; e < 2; e++) {
                    const int d = dp * 2 + e;
                    const float iG = acc[0][d] + bias[l][hcb + e];
                    const float fG = acc[1][d] + bias[l][16 + hcb + e];
                    const float gG = acc[2][d] + bias[l][32 + hcb + e];
                    const float oG = acc[3][d] + bias[l][48 + hcb + e];
                    const float iS = 0.5f + 0.5f * tanhapx(0.5f * iG);
                    const float fS = 0.5f + 0.5f * tanhapx(0.5f * fG);
                    const float oS = 0.5f + 0.5f * tanhapx(0.5f * oG);
                    const float cn = fS * c_reg[l][d] + iS * tanhapx(gG);
                    c_reg[l][d] = cn;
                    const float hv = oS * tanhapx(cn);
                    hv2[e] = __float2half_rn(hv);
                    if (l == 7) g_h7row[rg][r][hc0 + hcb + e] = hv;
                }
                *(__half2*)(hdst + hfrag16(r, hc0 + hcb)) = *(__half2*)hv2;
            }
            __syncthreads();
            if (tid == 0)
                asm volatile("st.release.gpu.global.u32 [%0], %1;"
                             :: "l"(&g_prog[rg * 16 + bh]),
                                "r"((unsigned)(t * 8 + l + 1)) : "memory");
        }

        if (tid < 16) {
            const unsigned tgt = (unsigned)(t * 8 + 8);
            unsigned v;
            const unsigned* fp = &g_prog[rg * 16 + tid];
            do {
                asm volatile("ld.acquire.gpu.global.u32 %0, [%1];" : "=r"(v) : "l"(fp));
                if (v >= tgt) break;
                __nanosleep(32);
            } while (1);
        }
        __syncthreads();

        // fc: 32 rows x 9 outs
        const int r2 = tid >> 2, og = tid & 3;
        float p0 = __ldg(&bfc[og]), p1 = __ldg(&bfc[og + 4]);
        float p2 = (og == 0) ? __ldg(&bfc[8]) : 0.f;
        for (int qq = 0; qq < 4; qq++) {
            __syncthreads();
#pragma unroll
            for (int q = 0; q < 4; q++) {
                const int i = tid + 128 * q;
                const int r = i >> 4, kq = (i & 15) << 2;
                float4 v = __ldcg((const float4*)&g_h7row[rg][r][qq * 64 + kq]);
                Gs[r][kq] = v.x; Gs[r][kq + 1] = v.y; Gs[r][kq + 2] = v.z; Gs[r][kq + 3] = v.w;
            }
            __syncthreads();
#pragma unroll 4
            for (int k = 0; k < 64; k++) {
                const float gv = Gs[r2][k];
                p0 += gv * Wfcs[og * 256 + qq * 64 + k];
                p1 += gv * Wfcs[(og + 4) * 256 + qq * 64 + k];
                if (og == 0) p2 += gv * Wfcs[8 * 256 + qq * 64 + k];
            }
        }
        __syncthreads();
        xs[r2][1 + og] = p0;
        xs[r2][1 + og + 4] = p1;
        if (og == 0) xs[r2][9] = p2;
        if (bh == 0) {
            out[(size_t)(row0 + r2) * (NSTEP * 9) + t * 9 + og] = p0;
            out[(size_t)(row0 + r2) * (NSTEP * 9) + t * 9 + og + 4] = p1;
            if (og == 0) out[(size_t)(row0 + r2) * (NSTEP * 9) + t * 9 + 8] = p2;
        }
        __syncthreads();
    }
}

extern "C" void kernel_launch(void* const* d_in, const int* in_sizes, int n_in,
                              void* d_out, int out_size) {
    const float* states = (const float*)d_in[0];
    const float* acts   = (const float*)d_in[1];
    const float* dts    = (const float*)d_in[2];
    const float* W1     = (const float*)d_in[3];
    const float* b1     = (const float*)d_in[4];
    const float* W2     = (const float*)d_in[5];
    const float* b2     = (const float*)d_in[6];
    const float* Wih0   = (const float*)d_in[7];
    const float* Whh0   = (const float*)d_in[8];
    const float* bih0   = (const float*)d_in[9];
    const float* bhh0   = (const float*)d_in[10];
    const float* Wih    = (const float*)d_in[11];
    const float* Whh    = (const float*)d_in[12];
    const float* bih    = (const float*)d_in[13];
    const float* bhh    = (const float*)d_in[14];
    const float* Wfc    = (const float*)d_in[15];
    const float* bfc    = (const float*)d_in[16];
    float* out = (float*)d_out;

    const int sm2 = 8 * 512 * 16;
    const int smr = 6272 * 4;
    cudaFuncSetAttribute(k_gemm2, cudaFuncAttributeMaxDynamicSharedMemorySize, sm2);
    cudaFuncSetAttribute(k_rollout, cudaFuncAttributeMaxDynamicSharedMemorySize, smr);

    k_prep_w<<<16384, 256>>>(Whh0, Wih, Whh);
    k_prep_w2t<<<64 * NC2H, 256>>>(W2);
    k_prep_small<<<146, 256>>>(Wih0);
    k_gemm1<<<16 * 118, 256>>>(states, acts, W1, b1);
    k_gemm2<<<512, 256, sm2>>>(b2);
    k_rollout<<<256, 128, smr>>>(states, acts, dts, bih0, bhh0,
                                 bih, bhh, Wfc, bfc, out);
}